// round 9
// baseline (speedup 1.0000x reference)
#include <cuda_runtime.h>

// ---------------- static device scratch (no allocations allowed) -------------
#define MAXN 50176
#define MAXE 800256
#define CAP  64    // per-warp smem edge cache in k_node (deg max ~45 here)
#define SCAN_B 256

struct __align__(16) Rec { float4 p; int src; int pad[3]; };   // 32B, one sector

__device__ __align__(16) float g_xh[(size_t)MAXN * 64];      // x @ W^T      [N,64]
__device__ __align__(16) float g_asrc[MAXN * 4];             // att_src . xh [N,4]
__device__ __align__(16) float g_adst[MAXN * 4];             // att_dst . xh [N,4]
__device__ Rec  g_rec[MAXE];                                 // dst-sorted {p,src}
__device__ int  g_deg[MAXN];                                 // in-degree
__device__ int  g_ptr[MAXN];                                 // CSR row starts
__device__ int  g_off[MAXN];                                 // scatter cursor
__device__ int  g_bsum[(MAXN + SCAN_B - 1) / SCAN_B + 1];
__device__ __align__(16) float g_v[64 * 4];                  // folded W_edge/att_edge

__device__ __forceinline__ float lrelu(float f) { return f > 0.f ? f : 0.2f * f; }

__device__ __forceinline__ float4 wsum4(float4 v) {
#pragma unroll
    for (int o = 16; o; o >>= 1) {
        v.x += __shfl_xor_sync(0xffffffffu, v.x, o);
        v.y += __shfl_xor_sync(0xffffffffu, v.y, o);
        v.z += __shfl_xor_sync(0xffffffffu, v.z, o);
        v.w += __shfl_xor_sync(0xffffffffu, v.w, o);
    }
    return v;
}

// ---------------- L0: zero histogram + asrc/adst + fold v ---------------------
__global__ void k_initv(const float* __restrict__ We, const float* __restrict__ att_edge,
                        int N) {
    int t = blockIdx.x * blockDim.x + threadIdx.x;
    if (t < N) g_deg[t] = 0;
    if (t < N * 4) { g_asrc[t] = 0.f; g_adst[t] = 0.f; }
    if (blockIdx.x == 0) {                 // 256 threads: fold W_edge with att_edge
        int d = threadIdx.x >> 2, h = threadIdx.x & 3;
        float s = 0.f;
#pragma unroll
        for (int c = 0; c < 16; c++)
            s += We[(h * 16 + c) * 64 + d] * att_edge[h * 16 + c];
        g_v[d * 4 + h] = s;
    }
}

// ---------------- L1: in-degree histogram -------------------------------------
__global__ void k_hist(const int* __restrict__ ei, int E) {
    int e = blockIdx.x * blockDim.x + threadIdx.x;
    if (e < E) atomicAdd(&g_deg[ei[E + e]], 1);
}

// ---------------- multi-block exclusive scan (3 kernels, parallel) ------------
__global__ void k_scanA(int N) {
    __shared__ int sh[SCAN_B];
    int t = threadIdx.x, b = blockIdx.x;
    int i = b * SCAN_B + t;
    sh[t] = (i < N) ? g_deg[i] : 0;
    __syncthreads();
#pragma unroll
    for (int o = SCAN_B / 2; o; o >>= 1) {
        if (t < o) sh[t] += sh[t + o];
        __syncthreads();
    }
    if (t == 0) g_bsum[b] = sh[0];
}
__global__ void k_scanB(int NB) {
    __shared__ int sh[1024];
    int t = threadIdx.x;
    int v = (t < NB) ? g_bsum[t] : 0;
    sh[t] = v;
    __syncthreads();
    for (int o = 1; o < 1024; o <<= 1) {
        int u = (t >= o) ? sh[t - o] : 0;
        __syncthreads();
        sh[t] += u;
        __syncthreads();
    }
    if (t < NB) g_bsum[t] = sh[t] - v;   // exclusive
}
__global__ void k_scanC(int N) {
    __shared__ int sh[SCAN_B];
    int t = threadIdx.x, b = blockIdx.x;
    int i = b * SCAN_B + t;
    int v = (i < N) ? g_deg[i] : 0;
    sh[t] = v;
    __syncthreads();
#pragma unroll
    for (int o = 1; o < SCAN_B; o <<= 1) {
        int u = (t >= o) ? sh[t - o] : 0;
        __syncthreads();
        sh[t] += u;
        __syncthreads();
    }
    if (i < N) {
        int off = g_bsum[b] + sh[t] - v;   // exclusive
        g_ptr[i] = off;
        g_off[i] = off;
    }
}

// ---------------- K1: register-W GEMM, broadcast-only smem --------------------
// tid = ch*4 + q. Thread holds W[ch][32q:32q+32) in 32 regs. Per node: 8 LDS.128
// (4 distinct banks/inst, broadcast over 8 channels) + 32 FMA; fold q via shfl.
__global__ void __launch_bounds__(256) k_xh(const float* __restrict__ x,
                                            const float* __restrict__ W,
                                            const float* __restrict__ att_src,
                                            const float* __restrict__ att_dst, int N) {
    __shared__ float4 sm[2048];            // 32KB: W staging first, then x tiles
    int tid  = threadIdx.x;
    int ch   = tid >> 2, q = tid & 3;
    int lane = tid & 31;
    int wrp  = tid >> 5;                   // warp id 0..7; head = wrp>>1

    // one-time: stage W coalesced, pull this thread's 32 weights into registers
    const float4* W4 = (const float4*)W;   // [64*128] floats = 2048 float4
    for (int i = tid; i < 2048; i += 256) sm[i] = W4[i];
    __syncthreads();
    float4 wr[8];
#pragma unroll
    for (int j = 0; j < 8; j++) wr[j] = sm[tid * 8 + j];   // W[ch][32q+4j .. +3]
    float ats = att_src[ch], atd = att_dst[ch];

    int tiles = (N + 15) >> 4;
    for (int tile = blockIdx.x; tile < tiles; tile += gridDim.x) {
        int base = tile << 4;
        __syncthreads();
        // stage 16 x-rows; row layout: quarter q at float4 idx r*36 + q*9 + j
        for (int i = tid; i < 512; i += 256) {
            int r = i >> 5, c4 = i & 31;
            int node = base + r;
            float4 v = (node < N) ? ((const float4*)x)[(size_t)node * 32 + c4]
                                  : make_float4(0.f, 0.f, 0.f, 0.f);
            sm[r * 36 + (c4 >> 3) * 9 + (c4 & 7)] = v;
        }
        __syncthreads();
        int nmax = min(16, N - base);
        for (int r = 0; r < nmax; r++) {
            const float4* xr = &sm[r * 36 + q * 9];
            float4 s4 = make_float4(0.f, 0.f, 0.f, 0.f);
#pragma unroll
            for (int j = 0; j < 8; j++) {
                float4 xv = xr[j];
                s4.x += wr[j].x * xv.x;
                s4.y += wr[j].y * xv.y;
                s4.z += wr[j].z * xv.z;
                s4.w += wr[j].w * xv.w;
            }
            float v = (s4.x + s4.y) + (s4.z + s4.w);
            v += __shfl_xor_sync(0xffffffffu, v, 1);   // fold q
            v += __shfl_xor_sync(0xffffffffu, v, 2);
            int node = base + r;
            if (q == 0) g_xh[(size_t)node * 64 + ch] = v;
            float s = v * ats, d = v * atd;            // same on all q lanes
#pragma unroll
            for (int o = 4; o <= 16; o <<= 1) {        // fold 8 channels in warp
                s += __shfl_xor_sync(0xffffffffu, s, o);
                d += __shfl_xor_sync(0xffffffffu, d, o);
            }
            int head = wrp >> 1;
            if (lane == 1) atomicAdd(&g_asrc[node * 4 + head], s);
            if (lane == 2) atomicAdd(&g_adst[node * 4 + head], d);
        }
    }
}

// ---------------- K2: chunked-staging thread-per-edge p + sorted scatter ------
__global__ void __launch_bounds__(128, 8) k_edge_p(const float* __restrict__ ea,
                                                   const int* __restrict__ ei, int E) {
    __shared__ float4 sE[128 * 9];   // 8 k-cols + 1 pad
    __shared__ float4 sV[64];
    int tid = threadIdx.x;
    int tile0 = blockIdx.x * 128;
    if (tid < 64) sV[tid] = ((const float4*)g_v)[tid];
    const float4* ea4 = (const float4*)ea;
    int e = tile0 + tid;
    float4 acc = make_float4(0.f, 0.f, 0.f, 0.f);
#pragma unroll
    for (int half = 0; half < 2; half++) {
        __syncthreads();
#pragma unroll
        for (int j = 0; j < 8; j++) {       // stage 128 rows x 8 float4, coalesced
            int i = tid + 128 * j;
            int row = i >> 3, col = i & 7;
            if (tile0 + row < E)
                sE[row * 9 + col] = ea4[(size_t)(tile0 + row) * 16 + half * 8 + col];
        }
        __syncthreads();
        if (e < E) {
#pragma unroll
            for (int k = 0; k < 8; k++) {
                float4 a  = sE[tid * 9 + k];
                int kk = half * 8 + k;
                float4 v0 = sV[4 * kk + 0];
                float4 v1 = sV[4 * kk + 1];
                float4 v2 = sV[4 * kk + 2];
                float4 v3 = sV[4 * kk + 3];
                acc.x += a.x * v0.x + a.y * v1.x + a.z * v2.x + a.w * v3.x;
                acc.y += a.x * v0.y + a.y * v1.y + a.z * v2.y + a.w * v3.y;
                acc.z += a.x * v0.z + a.y * v1.z + a.z * v2.z + a.w * v3.z;
                acc.w += a.x * v0.w + a.y * v1.w + a.z * v2.w + a.w * v3.w;
            }
        }
    }
    if (e >= E) return;
    int src = ei[e], dst = ei[E + e];
    int pos = atomicAdd(&g_off[dst], 1);
    g_rec[pos].p   = acc;     // same 32B sector
    g_rec[pos].src = src;
}

// ---------------- K5: single-pass softmax + aggregation (warp per node) -------
__global__ void __launch_bounds__(256) k_node(const float* __restrict__ bias,
                                              float* __restrict__ out, int N) {
    __shared__ float4 s_al[8][CAP];
    __shared__ int    s_src[8][CAP];
    int lane = threadIdx.x & 31, wi = threadIdx.x >> 5;
    int warp  = (blockIdx.x * blockDim.x + threadIdx.x) >> 5;
    int nwarp = (gridDim.x * blockDim.x) >> 5;
    float bs0 = bias[lane], bs1 = bias[32 + lane];
    bool lo = lane < 16;

    for (int n = warp; n < N; n += nwarp) {
        int beg = g_ptr[n], deg = g_deg[n];
        int dc  = min(deg, CAP);
        float4 ad = ((const float4*)g_adst)[n];
        float4 an = ((const float4*)g_asrc)[n];

        float4 sp = make_float4(0.f, 0.f, 0.f, 0.f);
        float4 d4 = make_float4(0.f, 0.f, 0.f, 0.f);
        for (int i = lane; i < dc; i += 32) {
            float4 p  = g_rec[beg + i].p;
            int src   = g_rec[beg + i].src;
            float4 as = ((const float4*)g_asrc)[src];
            float4 e4;
            e4.x = __expf(lrelu(as.x + ad.x + p.x));
            e4.y = __expf(lrelu(as.y + ad.y + p.y));
            e4.z = __expf(lrelu(as.z + ad.z + p.z));
            e4.w = __expf(lrelu(as.w + ad.w + p.w));
            sp.x += p.x; sp.y += p.y; sp.z += p.z; sp.w += p.w;
            d4.x += e4.x; d4.y += e4.y; d4.z += e4.z; d4.w += e4.w;
            s_al[wi][i] = e4; s_src[wi][i] = src;
        }
        for (int i = CAP + lane; i < deg; i += 32) {   // rare spill path
            float4 p  = g_rec[beg + i].p;
            int src   = g_rec[beg + i].src;
            float4 as = ((const float4*)g_asrc)[src];
            float4 e4;
            e4.x = __expf(lrelu(as.x + ad.x + p.x));
            e4.y = __expf(lrelu(as.y + ad.y + p.y));
            e4.z = __expf(lrelu(as.z + ad.z + p.z));
            e4.w = __expf(lrelu(as.w + ad.w + p.w));
            sp.x += p.x; sp.y += p.y; sp.z += p.z; sp.w += p.w;
            d4.x += e4.x; d4.y += e4.y; d4.z += e4.z; d4.w += e4.w;
            g_rec[beg + i].p = e4;
        }
        sp = wsum4(sp);
        d4 = wsum4(d4);
        float c = fmaxf((float)deg, 1.f);
        float4 esf;
        esf.x = __expf(lrelu(an.x + ad.x + sp.x / c));
        esf.y = __expf(lrelu(an.y + ad.y + sp.y / c));
        esf.z = __expf(lrelu(an.z + ad.z + sp.z / c));
        esf.w = __expf(lrelu(an.w + ad.w + sp.w / c));
        d4.x += esf.x; d4.y += esf.y; d4.z += esf.z; d4.w += esf.w;
        float4 inv;
        inv.x = 1.f / (d4.x + 1e-16f); inv.y = 1.f / (d4.y + 1e-16f);
        inv.z = 1.f / (d4.z + 1e-16f); inv.w = 1.f / (d4.w + 1e-16f);
        float invA = lo ? inv.x : inv.y;
        float invB = lo ? inv.z : inv.w;
        if (deg > CAP) __threadfence_block();
        __syncwarp();

        float acc0 = 0.f, acc1 = 0.f;
        int j = 0;
        for (; j + 2 <= dc; j += 2) {
            float4 a0 = s_al[wi][j];
            float4 a1 = s_al[wi][j + 1];
            const float* r0 = &g_xh[(size_t)s_src[wi][j] * 64];
            const float* r1 = &g_xh[(size_t)s_src[wi][j + 1] * 64];
            float x00 = r0[lane], x01 = r0[32 + lane];
            float x10 = r1[lane], x11 = r1[32 + lane];
            acc0 += (lo ? a0.x : a0.y) * invA * x00;
            acc1 += (lo ? a0.z : a0.w) * invB * x01;
            acc0 += (lo ? a1.x : a1.y) * invA * x10;
            acc1 += (lo ? a1.z : a1.w) * invB * x11;
        }
        if (j < dc) {
            float4 a0 = s_al[wi][j];
            const float* r0 = &g_xh[(size_t)s_src[wi][j] * 64];
            acc0 += (lo ? a0.x : a0.y) * invA * r0[lane];
            acc1 += (lo ? a0.z : a0.w) * invB * r0[32 + lane];
        }
        for (int k = CAP; k < deg; k++) {   // rare spill path
            float4 a0 = g_rec[beg + k].p;
            const float* r0 = &g_xh[(size_t)g_rec[beg + k].src * 64];
            acc0 += (lo ? a0.x : a0.y) * invA * r0[lane];
            acc1 += (lo ? a0.z : a0.w) * invB * r0[32 + lane];
        }
        {   // self-loop contribution
            const float* rn = &g_xh[(size_t)n * 64];
            acc0 += (lo ? esf.x : esf.y) * invA * rn[lane];
            acc1 += (lo ? esf.z : esf.w) * invB * rn[32 + lane];
        }
        out[(size_t)n * 64 + lane]      = acc0 + bs0;
        out[(size_t)n * 64 + 32 + lane] = acc1 + bs1;
        __syncwarp();
    }
}

// -----------------------------------------------------------------------------
extern "C" void kernel_launch(void* const* d_in, const int* in_sizes, int n_in,
                              void* d_out, int out_size) {
    (void)n_in; (void)out_size;
    const float* x        = (const float*)d_in[0];
    const int*   ei       = (const int*)d_in[1];
    const float* ea       = (const float*)d_in[2];
    const float* W        = (const float*)d_in[3];
    const float* We       = (const float*)d_in[4];
    const float* att_src  = (const float*)d_in[5];
    const float* att_dst  = (const float*)d_in[6];
    const float* att_edge = (const float*)d_in[7];
    const float* bias     = (const float*)d_in[8];
    float* out = (float*)d_out;

    int N = in_sizes[0] / 128;   // x is [N,128]
    int E = in_sizes[1] / 2;     // edge_index is [2,E]
    int NB = (N + SCAN_B - 1) / SCAN_B;

    k_initv <<<(N * 4 + 255) / 256, 256>>>(We, att_edge, N); // 0
    k_hist  <<<(E + 255) / 256, 256>>>(ei, E);               // 1
    k_scanA <<<NB, SCAN_B>>>(N);                             // 2
    k_xh    <<<(N + 15) / 16, 256>>>(x, W, att_src, att_dst, N); // 3 <- profiled
    k_scanB <<<1, 1024>>>(NB);                               // 4
    k_scanC <<<NB, SCAN_B>>>(N);                             // 5
    k_edge_p<<<(E + 127) / 128, 128>>>(ea, ei, E);           // 6
    k_node  <<<1480, 256>>>(bias, out, N);                   // 7
}

// round 10
// speedup vs baseline: 1.9431x; 1.9431x over previous
#include <cuda_runtime.h>

// ---------------- static device scratch (no allocations allowed) -------------
#define MAXN 50176
#define MAXE 800256
#define CAP  64    // per-warp smem edge cache in k_node (deg max ~45 here)
#define SCAN_B 256

struct __align__(16) Rec { float4 p; int src; int pad[3]; };   // 32B, one sector

__device__ __align__(16) float g_xh[(size_t)MAXN * 64];      // x @ W^T      [N,64]
__device__ __align__(16) float g_asrc[MAXN * 4];             // att_src . xh [N,4]
__device__ __align__(16) float g_adst[MAXN * 4];             // att_dst . xh [N,4]
__device__ Rec  g_rec[MAXE];                                 // dst-sorted {p,src}
__device__ int  g_deg[MAXN];                                 // in-degree
__device__ int  g_ptr[MAXN];                                 // CSR row starts
__device__ int  g_off[MAXN];                                 // scatter cursor
__device__ int  g_bsum[(MAXN + SCAN_B - 1) / SCAN_B + 1];
__device__ __align__(16) float g_v[64 * 4];                  // folded W_edge/att_edge

__device__ __forceinline__ float lrelu(float f) { return f > 0.f ? f : 0.2f * f; }

__device__ __forceinline__ float4 wsum4(float4 v) {
#pragma unroll
    for (int o = 16; o; o >>= 1) {
        v.x += __shfl_xor_sync(0xffffffffu, v.x, o);
        v.y += __shfl_xor_sync(0xffffffffu, v.y, o);
        v.z += __shfl_xor_sync(0xffffffffu, v.z, o);
        v.w += __shfl_xor_sync(0xffffffffu, v.w, o);
    }
    return v;
}

// ---------------- L0: zero histogram + fold v ----------------------------------
__global__ void k_initv(const float* __restrict__ We, const float* __restrict__ att_edge,
                        int N) {
    int t = blockIdx.x * blockDim.x + threadIdx.x;
    if (t < N) g_deg[t] = 0;
    if (blockIdx.x == 0) {                 // 256 threads: fold W_edge with att_edge
        int d = threadIdx.x >> 2, h = threadIdx.x & 3;
        float s = 0.f;
#pragma unroll
        for (int c = 0; c < 16; c++)
            s += We[(h * 16 + c) * 64 + d] * att_edge[h * 16 + c];
        g_v[d * 4 + h] = s;
    }
}

// ---------------- L1: in-degree histogram -------------------------------------
__global__ void k_hist(const int* __restrict__ ei, int E) {
    int e = blockIdx.x * blockDim.x + threadIdx.x;
    if (e < E) atomicAdd(&g_deg[ei[E + e]], 1);
}

// ---------------- multi-block exclusive scan (3 kernels, parallel) ------------
__global__ void k_scanA(int N) {
    __shared__ int sh[SCAN_B];
    int t = threadIdx.x, b = blockIdx.x;
    int i = b * SCAN_B + t;
    sh[t] = (i < N) ? g_deg[i] : 0;
    __syncthreads();
#pragma unroll
    for (int o = SCAN_B / 2; o; o >>= 1) {
        if (t < o) sh[t] += sh[t + o];
        __syncthreads();
    }
    if (t == 0) g_bsum[b] = sh[0];
}
__global__ void k_scanB(int NB) {
    __shared__ int sh[1024];
    int t = threadIdx.x;
    int v = (t < NB) ? g_bsum[t] : 0;
    sh[t] = v;
    __syncthreads();
    for (int o = 1; o < 1024; o <<= 1) {
        int u = (t >= o) ? sh[t - o] : 0;
        __syncthreads();
        sh[t] += u;
        __syncthreads();
    }
    if (t < NB) g_bsum[t] = sh[t] - v;   // exclusive
}
__global__ void k_scanC(int N) {
    __shared__ int sh[SCAN_B];
    int t = threadIdx.x, b = blockIdx.x;
    int i = b * SCAN_B + t;
    int v = (i < N) ? g_deg[i] : 0;
    sh[t] = v;
    __syncthreads();
#pragma unroll
    for (int o = 1; o < SCAN_B; o <<= 1) {
        int u = (t >= o) ? sh[t - o] : 0;
        __syncthreads();
        sh[t] += u;
        __syncthreads();
    }
    if (i < N) {
        int off = g_bsum[b] + sh[t] - v;   // exclusive
        g_ptr[i] = off;
        g_off[i] = off;
    }
}

// ---------------- K1: register-tiled GEMM xh = x @ W^T ------------------------
// Block tile 64ch x 64nodes; thread tile 4ch x 4nodes (16 FMA per 2 LDS.128).
// W and x stored k-major in smem, row pitch 68 floats (17 float4, conflict-free).
#define PITCH 68
__global__ void __launch_bounds__(256) k_xh(const float* __restrict__ x,
                                            const float* __restrict__ W,
                                            const float* __restrict__ att_src,
                                            const float* __restrict__ att_dst, int N) {
    __shared__ float sW[128 * PITCH];   // [k][ch]   34KB
    __shared__ float sX[128 * PITCH];   // [k][node] 34KB
    int tid = threadIdx.x;
    int tc = tid & 15, tn = tid >> 4;   // ch-group, node-group
    int base = blockIdx.x * 64;

    // stage W transposed: read W[c][4k4..+3] coalesced, write k-major
    const float4* W4 = (const float4*)W;
    for (int i = tid; i < 64 * 32; i += 256) {
        int c = i >> 5, k4 = i & 31;
        float4 w = W4[c * 32 + k4];
        sW[(4 * k4 + 0) * PITCH + c] = w.x;
        sW[(4 * k4 + 1) * PITCH + c] = w.y;
        sW[(4 * k4 + 2) * PITCH + c] = w.z;
        sW[(4 * k4 + 3) * PITCH + c] = w.w;
    }
    // stage x tile transposed
    const float4* x4 = (const float4*)x;
    for (int i = tid; i < 64 * 32; i += 256) {
        int r = i >> 5, k4 = i & 31;
        int node = base + r;
        float4 v = (node < N) ? x4[(size_t)node * 32 + k4]
                              : make_float4(0.f, 0.f, 0.f, 0.f);
        sX[(4 * k4 + 0) * PITCH + r] = v.x;
        sX[(4 * k4 + 1) * PITCH + r] = v.y;
        sX[(4 * k4 + 2) * PITCH + r] = v.z;
        sX[(4 * k4 + 3) * PITCH + r] = v.w;
    }
    __syncthreads();

    float acc[4][4];
#pragma unroll
    for (int i = 0; i < 4; i++)
#pragma unroll
        for (int j = 0; j < 4; j++) acc[i][j] = 0.f;

#pragma unroll 4
    for (int k = 0; k < 128; k++) {
        float4 w  = *(const float4*)&sW[k * PITCH + 4 * tc];
        float4 xv = *(const float4*)&sX[k * PITCH + 4 * tn];
        acc[0][0] += w.x * xv.x; acc[0][1] += w.x * xv.y; acc[0][2] += w.x * xv.z; acc[0][3] += w.x * xv.w;
        acc[1][0] += w.y * xv.x; acc[1][1] += w.y * xv.y; acc[1][2] += w.y * xv.z; acc[1][3] += w.y * xv.w;
        acc[2][0] += w.z * xv.x; acc[2][1] += w.z * xv.y; acc[2][2] += w.z * xv.z; acc[2][3] += w.z * xv.w;
        acc[3][0] += w.w * xv.x; acc[3][1] += w.w * xv.y; acc[3][2] += w.w * xv.z; acc[3][3] += w.w * xv.w;
    }

    // epilogue: xh float4 stores + direct a_src/a_dst (node owned by this block)
    float4 ats = ((const float4*)att_src)[tc];
    float4 atd = ((const float4*)att_dst)[tc];
    int head = tc >> 2;
#pragma unroll
    for (int j = 0; j < 4; j++) {
        int node = base + 4 * tn + j;
        if (node >= N) continue;
        *(float4*)&g_xh[(size_t)node * 64 + 4 * tc] =
            make_float4(acc[0][j], acc[1][j], acc[2][j], acc[3][j]);
        float s = acc[0][j] * ats.x + acc[1][j] * ats.y + acc[2][j] * ats.z + acc[3][j] * ats.w;
        float d = acc[0][j] * atd.x + acc[1][j] * atd.y + acc[2][j] * atd.z + acc[3][j] * atd.w;
        s += __shfl_xor_sync(0xffffffffu, s, 1);  d += __shfl_xor_sync(0xffffffffu, d, 1);
        s += __shfl_xor_sync(0xffffffffu, s, 2);  d += __shfl_xor_sync(0xffffffffu, d, 2);
        if ((tc & 3) == 0) {
            g_asrc[node * 4 + head] = s;
            g_adst[node * 4 + head] = d;
        }
    }
}

// ---------------- K2: chunked-staging thread-per-edge p + sorted scatter ------
__global__ void __launch_bounds__(128, 8) k_edge_p(const float* __restrict__ ea,
                                                   const int* __restrict__ ei, int E) {
    __shared__ float4 sE[128 * 9];   // 8 k-cols + 1 pad
    __shared__ float4 sV[64];
    int tid = threadIdx.x;
    int tile0 = blockIdx.x * 128;
    if (tid < 64) sV[tid] = ((const float4*)g_v)[tid];
    const float4* ea4 = (const float4*)ea;
    int e = tile0 + tid;
    float4 acc = make_float4(0.f, 0.f, 0.f, 0.f);
#pragma unroll
    for (int half = 0; half < 2; half++) {
        __syncthreads();
#pragma unroll
        for (int j = 0; j < 8; j++) {       // stage 128 rows x 8 float4, coalesced
            int i = tid + 128 * j;
            int row = i >> 3, col = i & 7;
            if (tile0 + row < E)
                sE[row * 9 + col] = ea4[(size_t)(tile0 + row) * 16 + half * 8 + col];
        }
        __syncthreads();
        if (e < E) {
#pragma unroll
            for (int k = 0; k < 8; k++) {
                float4 a  = sE[tid * 9 + k];
                int kk = half * 8 + k;
                float4 v0 = sV[4 * kk + 0];
                float4 v1 = sV[4 * kk + 1];
                float4 v2 = sV[4 * kk + 2];
                float4 v3 = sV[4 * kk + 3];
                acc.x += a.x * v0.x + a.y * v1.x + a.z * v2.x + a.w * v3.x;
                acc.y += a.x * v0.y + a.y * v1.y + a.z * v2.y + a.w * v3.y;
                acc.z += a.x * v0.z + a.y * v1.z + a.z * v2.z + a.w * v3.z;
                acc.w += a.x * v0.w + a.y * v1.w + a.z * v2.w + a.w * v3.w;
            }
        }
    }
    if (e >= E) return;
    int src = ei[e], dst = ei[E + e];
    int pos = atomicAdd(&g_off[dst], 1);
    g_rec[pos].p   = acc;     // same 32B sector
    g_rec[pos].src = src;
}

// ---------------- K5: single-pass softmax + aggregation (warp per node) -------
__global__ void __launch_bounds__(256) k_node(const float* __restrict__ bias,
                                              float* __restrict__ out, int N) {
    __shared__ float4 s_al[8][CAP];
    __shared__ int    s_src[8][CAP];
    int lane = threadIdx.x & 31, wi = threadIdx.x >> 5;
    int warp  = (blockIdx.x * blockDim.x + threadIdx.x) >> 5;
    int nwarp = (gridDim.x * blockDim.x) >> 5;
    float bs0 = bias[lane], bs1 = bias[32 + lane];
    bool lo = lane < 16;

    for (int n = warp; n < N; n += nwarp) {
        int beg = g_ptr[n], deg = g_deg[n];
        int dc  = min(deg, CAP);
        float4 ad = ((const float4*)g_adst)[n];
        float4 an = ((const float4*)g_asrc)[n];

        float4 sp = make_float4(0.f, 0.f, 0.f, 0.f);
        float4 d4 = make_float4(0.f, 0.f, 0.f, 0.f);
        for (int i = lane; i < dc; i += 32) {
            float4 p  = g_rec[beg + i].p;
            int src   = g_rec[beg + i].src;
            float4 as = ((const float4*)g_asrc)[src];
            float4 e4;
            e4.x = __expf(lrelu(as.x + ad.x + p.x));
            e4.y = __expf(lrelu(as.y + ad.y + p.y));
            e4.z = __expf(lrelu(as.z + ad.z + p.z));
            e4.w = __expf(lrelu(as.w + ad.w + p.w));
            sp.x += p.x; sp.y += p.y; sp.z += p.z; sp.w += p.w;
            d4.x += e4.x; d4.y += e4.y; d4.z += e4.z; d4.w += e4.w;
            s_al[wi][i] = e4; s_src[wi][i] = src;
        }
        for (int i = CAP + lane; i < deg; i += 32) {   // rare spill path
            float4 p  = g_rec[beg + i].p;
            int src   = g_rec[beg + i].src;
            float4 as = ((const float4*)g_asrc)[src];
            float4 e4;
            e4.x = __expf(lrelu(as.x + ad.x + p.x));
            e4.y = __expf(lrelu(as.y + ad.y + p.y));
            e4.z = __expf(lrelu(as.z + ad.z + p.z));
            e4.w = __expf(lrelu(as.w + ad.w + p.w));
            sp.x += p.x; sp.y += p.y; sp.z += p.z; sp.w += p.w;
            d4.x += e4.x; d4.y += e4.y; d4.z += e4.z; d4.w += e4.w;
            g_rec[beg + i].p = e4;
        }
        sp = wsum4(sp);
        d4 = wsum4(d4);
        float c = fmaxf((float)deg, 1.f);
        float4 esf;
        esf.x = __expf(lrelu(an.x + ad.x + sp.x / c));
        esf.y = __expf(lrelu(an.y + ad.y + sp.y / c));
        esf.z = __expf(lrelu(an.z + ad.z + sp.z / c));
        esf.w = __expf(lrelu(an.w + ad.w + sp.w / c));
        d4.x += esf.x; d4.y += esf.y; d4.z += esf.z; d4.w += esf.w;
        float4 inv;
        inv.x = 1.f / (d4.x + 1e-16f); inv.y = 1.f / (d4.y + 1e-16f);
        inv.z = 1.f / (d4.z + 1e-16f); inv.w = 1.f / (d4.w + 1e-16f);
        float invA = lo ? inv.x : inv.y;
        float invB = lo ? inv.z : inv.w;
        if (deg > CAP) __threadfence_block();
        __syncwarp();

        float acc0 = 0.f, acc1 = 0.f;
        int j = 0;
        for (; j + 2 <= dc; j += 2) {
            float4 a0 = s_al[wi][j];
            float4 a1 = s_al[wi][j + 1];
            const float* r0 = &g_xh[(size_t)s_src[wi][j] * 64];
            const float* r1 = &g_xh[(size_t)s_src[wi][j + 1] * 64];
            float x00 = r0[lane], x01 = r0[32 + lane];
            float x10 = r1[lane], x11 = r1[32 + lane];
            acc0 += (lo ? a0.x : a0.y) * invA * x00;
            acc1 += (lo ? a0.z : a0.w) * invB * x01;
            acc0 += (lo ? a1.x : a1.y) * invA * x10;
            acc1 += (lo ? a1.z : a1.w) * invB * x11;
        }
        if (j < dc) {
            float4 a0 = s_al[wi][j];
            const float* r0 = &g_xh[(size_t)s_src[wi][j] * 64];
            acc0 += (lo ? a0.x : a0.y) * invA * r0[lane];
            acc1 += (lo ? a0.z : a0.w) * invB * r0[32 + lane];
        }
        for (int k = CAP; k < deg; k++) {   // rare spill path
            float4 a0 = g_rec[beg + k].p;
            const float* r0 = &g_xh[(size_t)g_rec[beg + k].src * 64];
            acc0 += (lo ? a0.x : a0.y) * invA * r0[lane];
            acc1 += (lo ? a0.z : a0.w) * invB * r0[32 + lane];
        }
        {   // self-loop contribution
            const float* rn = &g_xh[(size_t)n * 64];
            acc0 += (lo ? esf.x : esf.y) * invA * rn[lane];
            acc1 += (lo ? esf.z : esf.w) * invB * rn[32 + lane];
        }
        out[(size_t)n * 64 + lane]      = acc0 + bs0;
        out[(size_t)n * 64 + 32 + lane] = acc1 + bs1;
        __syncwarp();
    }
}

// -----------------------------------------------------------------------------
extern "C" void kernel_launch(void* const* d_in, const int* in_sizes, int n_in,
                              void* d_out, int out_size) {
    (void)n_in; (void)out_size;
    const float* x        = (const float*)d_in[0];
    const int*   ei       = (const int*)d_in[1];
    const float* ea       = (const float*)d_in[2];
    const float* W        = (const float*)d_in[3];
    const float* We       = (const float*)d_in[4];
    const float* att_src  = (const float*)d_in[5];
    const float* att_dst  = (const float*)d_in[6];
    const float* att_edge = (const float*)d_in[7];
    const float* bias     = (const float*)d_in[8];
    float* out = (float*)d_out;

    int N = in_sizes[0] / 128;   // x is [N,128]
    int E = in_sizes[1] / 2;     // edge_index is [2,E]
    int NB = (N + SCAN_B - 1) / SCAN_B;

    k_initv <<<(N + 255) / 256, 256>>>(We, att_edge, N);     // 0
    k_hist  <<<(E + 255) / 256, 256>>>(ei, E);               // 1
    k_scanA <<<NB, SCAN_B>>>(N);                             // 2
    k_xh    <<<(N + 63) / 64, 256>>>(x, W, att_src, att_dst, N); // 3 <- profiled
    k_scanB <<<1, 1024>>>(NB);                               // 4
    k_scanC <<<NB, SCAN_B>>>(N);                             // 5
    k_edge_p<<<(E + 127) / 128, 128>>>(ea, ei, E);           // 6
    k_node  <<<1480, 256>>>(bias, out, N);                   // 7
}

// round 11
// speedup vs baseline: 2.1476x; 1.1053x over previous
#include <cuda_runtime.h>

// ---------------- static device scratch (no allocations allowed) -------------
#define MAXN 50176
#define MAXE 800256
#define CAP  64    // per-warp smem edge cache in k_node (deg max ~45 here)
#define SCAN_B 256

struct __align__(16) Rec { float4 p; int src; int pad[3]; };   // 32B, one sector

__device__ __align__(16) float g_xh[(size_t)MAXN * 64];      // x @ W^T      [N,64]
__device__ __align__(16) float g_asrc[MAXN * 4];             // att_src . xh [N,4]
__device__ __align__(16) float g_adst[MAXN * 4];             // att_dst . xh [N,4]
__device__ __align__(16) float g_wt[128 * 64];               // W^T (k-major) [k][ch]
__device__ Rec  g_rec[MAXE];                                 // dst-sorted {p,src}
__device__ int  g_deg[MAXN];                                 // in-degree
__device__ int  g_ptr[MAXN];                                 // CSR row starts
__device__ int  g_off[MAXN];                                 // scatter cursor
__device__ int  g_bsum[(MAXN + SCAN_B - 1) / SCAN_B + 1];
__device__ __align__(16) float g_v[64 * 4];                  // folded W_edge/att_edge

__device__ __forceinline__ float lrelu(float f) { return f > 0.f ? f : 0.2f * f; }

__device__ __forceinline__ float4 wsum4(float4 v) {
#pragma unroll
    for (int o = 16; o; o >>= 1) {
        v.x += __shfl_xor_sync(0xffffffffu, v.x, o);
        v.y += __shfl_xor_sync(0xffffffffu, v.y, o);
        v.z += __shfl_xor_sync(0xffffffffu, v.z, o);
        v.w += __shfl_xor_sync(0xffffffffu, v.w, o);
    }
    return v;
}

// ---------------- L0: zero histogram + fold v + transpose W -------------------
__global__ void k_initv(const float* __restrict__ We, const float* __restrict__ att_edge,
                        const float* __restrict__ W, int N) {
    int t = blockIdx.x * blockDim.x + threadIdx.x;
    if (t < N) g_deg[t] = 0;
    if (t < 128 * 64) {                    // W^T: g_wt[k][c] = W[c][k]
        int k = t >> 6, c = t & 63;
        g_wt[t] = W[c * 128 + k];
    }
    if (blockIdx.x == 0) {                 // 256 threads: fold W_edge with att_edge
        int d = threadIdx.x >> 2, h = threadIdx.x & 3;
        float s = 0.f;
#pragma unroll
        for (int c = 0; c < 16; c++)
            s += We[(h * 16 + c) * 64 + d] * att_edge[h * 16 + c];
        g_v[d * 4 + h] = s;
    }
}

// ---------------- L1: in-degree histogram -------------------------------------
__global__ void k_hist(const int* __restrict__ ei, int E) {
    int e = blockIdx.x * blockDim.x + threadIdx.x;
    if (e < E) atomicAdd(&g_deg[ei[E + e]], 1);
}

// ---------------- multi-block exclusive scan (3 kernels, parallel) ------------
__global__ void k_scanA(int N) {
    __shared__ int sh[SCAN_B];
    int t = threadIdx.x, b = blockIdx.x;
    int i = b * SCAN_B + t;
    sh[t] = (i < N) ? g_deg[i] : 0;
    __syncthreads();
#pragma unroll
    for (int o = SCAN_B / 2; o; o >>= 1) {
        if (t < o) sh[t] += sh[t + o];
        __syncthreads();
    }
    if (t == 0) g_bsum[b] = sh[0];
}
__global__ void k_scanB(int NB) {
    __shared__ int sh[1024];
    int t = threadIdx.x;
    int v = (t < NB) ? g_bsum[t] : 0;
    sh[t] = v;
    __syncthreads();
    for (int o = 1; o < 1024; o <<= 1) {
        int u = (t >= o) ? sh[t - o] : 0;
        __syncthreads();
        sh[t] += u;
        __syncthreads();
    }
    if (t < NB) g_bsum[t] = sh[t] - v;   // exclusive
}
__global__ void k_scanC(int N) {
    __shared__ int sh[SCAN_B];
    int t = threadIdx.x, b = blockIdx.x;
    int i = b * SCAN_B + t;
    int v = (i < N) ? g_deg[i] : 0;
    sh[t] = v;
    __syncthreads();
#pragma unroll
    for (int o = 1; o < SCAN_B; o <<= 1) {
        int u = (t >= o) ? sh[t - o] : 0;
        __syncthreads();
        sh[t] += u;
        __syncthreads();
    }
    if (i < N) {
        int off = g_bsum[b] + sh[t] - v;   // exclusive
        g_ptr[i] = off;
        g_off[i] = off;
    }
}

// ---------------- K1: register-tiled GEMM, conflict-free staging --------------
// Block tile 64ch x 64nodes; thread tile 4ch x 4nodes.
// W staged k-major from pre-transposed g_wt (straight float4 copy).
// x staged ROW-major (pitch 132 floats): staging writes conflict-free float4,
// main-loop x reads are warp broadcasts (only 2 node-groups per warp).
#define XPITCH 132
__global__ void __launch_bounds__(256) k_xh(const float* __restrict__ x,
                                            const float* __restrict__ att_src,
                                            const float* __restrict__ att_dst, int N) {
    __shared__ float sWT[128 * 64];       // [k][ch]     32KB
    __shared__ float sX[64 * XPITCH];     // [node][k]   33KB
    int tid = threadIdx.x;
    int tc = tid & 15, tn = tid >> 4;     // ch-group, node-group
    int base = blockIdx.x * 64;

    // stage W^T: linear conflict-free float4 copy
    {
        const float4* wt4 = (const float4*)g_wt;
        float4* s4 = (float4*)sWT;
        for (int i = tid; i < 2048; i += 256) s4[i] = wt4[i];
    }
    // stage x tile row-major: coalesced float4 reads, conflict-free writes
    {
        const float4* x4 = (const float4*)x;
        for (int i = tid; i < 64 * 32; i += 256) {
            int r = i >> 5, k4 = i & 31;
            int node = base + r;
            float4 v = (node < N) ? x4[(size_t)node * 32 + k4]
                                  : make_float4(0.f, 0.f, 0.f, 0.f);
            *(float4*)&sX[r * XPITCH + 4 * k4] = v;
        }
    }
    __syncthreads();

    float acc[4][4];
#pragma unroll
    for (int i = 0; i < 4; i++)
#pragma unroll
        for (int j = 0; j < 4; j++) acc[i][j] = 0.f;

    const float* xr0 = &sX[(4 * tn + 0) * XPITCH];
    const float* xr1 = &sX[(4 * tn + 1) * XPITCH];
    const float* xr2 = &sX[(4 * tn + 2) * XPITCH];
    const float* xr3 = &sX[(4 * tn + 3) * XPITCH];
    const float4* w4 = (const float4*)sWT;

#pragma unroll 8
    for (int k = 0; k < 128; k++) {
        float4 w  = w4[k * 16 + tc];
        float x0 = xr0[k], x1 = xr1[k], x2 = xr2[k], x3 = xr3[k];
        acc[0][0] += w.x * x0; acc[0][1] += w.x * x1; acc[0][2] += w.x * x2; acc[0][3] += w.x * x3;
        acc[1][0] += w.y * x0; acc[1][1] += w.y * x1; acc[1][2] += w.y * x2; acc[1][3] += w.y * x3;
        acc[2][0] += w.z * x0; acc[2][1] += w.z * x1; acc[2][2] += w.z * x2; acc[2][3] += w.z * x3;
        acc[3][0] += w.w * x0; acc[3][1] += w.w * x1; acc[3][2] += w.w * x2; acc[3][3] += w.w * x3;
    }

    // epilogue: xh float4 stores + direct a_src/a_dst (node owned by this block)
    float4 ats = ((const float4*)att_src)[tc];
    float4 atd = ((const float4*)att_dst)[tc];
    int head = tc >> 2;
#pragma unroll
    for (int j = 0; j < 4; j++) {
        int node = base + 4 * tn + j;
        if (node >= N) continue;
        *(float4*)&g_xh[(size_t)node * 64 + 4 * tc] =
            make_float4(acc[0][j], acc[1][j], acc[2][j], acc[3][j]);
        float s = acc[0][j] * ats.x + acc[1][j] * ats.y + acc[2][j] * ats.z + acc[3][j] * ats.w;
        float d = acc[0][j] * atd.x + acc[1][j] * atd.y + acc[2][j] * atd.z + acc[3][j] * atd.w;
        s += __shfl_xor_sync(0xffffffffu, s, 1);  d += __shfl_xor_sync(0xffffffffu, d, 1);
        s += __shfl_xor_sync(0xffffffffu, s, 2);  d += __shfl_xor_sync(0xffffffffu, d, 2);
        if ((tc & 3) == 0) {
            g_asrc[node * 4 + head] = s;
            g_adst[node * 4 + head] = d;
        }
    }
}

// ---------------- K2: chunked-staging thread-per-edge p + sorted scatter ------
__global__ void __launch_bounds__(128, 8) k_edge_p(const float* __restrict__ ea,
                                                   const int* __restrict__ ei, int E) {
    __shared__ float4 sE[128 * 9];   // 8 k-cols + 1 pad
    __shared__ float4 sV[64];
    int tid = threadIdx.x;
    int tile0 = blockIdx.x * 128;
    if (tid < 64) sV[tid] = ((const float4*)g_v)[tid];
    const float4* ea4 = (const float4*)ea;
    int e = tile0 + tid;
    float4 acc = make_float4(0.f, 0.f, 0.f, 0.f);
#pragma unroll
    for (int half = 0; half < 2; half++) {
        __syncthreads();
#pragma unroll
        for (int j = 0; j < 8; j++) {       // stage 128 rows x 8 float4, coalesced
            int i = tid + 128 * j;
            int row = i >> 3, col = i & 7;
            if (tile0 + row < E)
                sE[row * 9 + col] = ea4[(size_t)(tile0 + row) * 16 + half * 8 + col];
        }
        __syncthreads();
        if (e < E) {
#pragma unroll
            for (int k = 0; k < 8; k++) {
                float4 a  = sE[tid * 9 + k];
                int kk = half * 8 + k;
                float4 v0 = sV[4 * kk + 0];
                float4 v1 = sV[4 * kk + 1];
                float4 v2 = sV[4 * kk + 2];
                float4 v3 = sV[4 * kk + 3];
                acc.x += a.x * v0.x + a.y * v1.x + a.z * v2.x + a.w * v3.x;
                acc.y += a.x * v0.y + a.y * v1.y + a.z * v2.y + a.w * v3.y;
                acc.z += a.x * v0.z + a.y * v1.z + a.z * v2.z + a.w * v3.z;
                acc.w += a.x * v0.w + a.y * v1.w + a.z * v2.w + a.w * v3.w;
            }
        }
    }
    if (e >= E) return;
    int src = ei[e], dst = ei[E + e];
    int pos = atomicAdd(&g_off[dst], 1);
    g_rec[pos].p   = acc;     // same 32B sector
    g_rec[pos].src = src;
}

// ---------------- K5: single-pass softmax + aggregation (warp per node) -------
__global__ void __launch_bounds__(256) k_node(const float* __restrict__ bias,
                                              float* __restrict__ out, int N) {
    __shared__ float4 s_al[8][CAP];
    __shared__ int    s_src[8][CAP];
    int lane = threadIdx.x & 31, wi = threadIdx.x >> 5;
    int warp  = (blockIdx.x * blockDim.x + threadIdx.x) >> 5;
    int nwarp = (gridDim.x * blockDim.x) >> 5;
    float bs0 = bias[lane], bs1 = bias[32 + lane];
    bool lo = lane < 16;

    for (int n = warp; n < N; n += nwarp) {
        int beg = g_ptr[n], deg = g_deg[n];
        int dc  = min(deg, CAP);
        float4 ad = ((const float4*)g_adst)[n];
        float4 an = ((const float4*)g_asrc)[n];

        float4 sp = make_float4(0.f, 0.f, 0.f, 0.f);
        float4 d4 = make_float4(0.f, 0.f, 0.f, 0.f);
        for (int i = lane; i < dc; i += 32) {
            float4 p  = g_rec[beg + i].p;
            int src   = g_rec[beg + i].src;
            float4 as = ((const float4*)g_asrc)[src];
            float4 e4;
            e4.x = __expf(lrelu(as.x + ad.x + p.x));
            e4.y = __expf(lrelu(as.y + ad.y + p.y));
            e4.z = __expf(lrelu(as.z + ad.z + p.z));
            e4.w = __expf(lrelu(as.w + ad.w + p.w));
            sp.x += p.x; sp.y += p.y; sp.z += p.z; sp.w += p.w;
            d4.x += e4.x; d4.y += e4.y; d4.z += e4.z; d4.w += e4.w;
            s_al[wi][i] = e4; s_src[wi][i] = src;
        }
        for (int i = CAP + lane; i < deg; i += 32) {   // rare spill path
            float4 p  = g_rec[beg + i].p;
            int src   = g_rec[beg + i].src;
            float4 as = ((const float4*)g_asrc)[src];
            float4 e4;
            e4.x = __expf(lrelu(as.x + ad.x + p.x));
            e4.y = __expf(lrelu(as.y + ad.y + p.y));
            e4.z = __expf(lrelu(as.z + ad.z + p.z));
            e4.w = __expf(lrelu(as.w + ad.w + p.w));
            sp.x += p.x; sp.y += p.y; sp.z += p.z; sp.w += p.w;
            d4.x += e4.x; d4.y += e4.y; d4.z += e4.z; d4.w += e4.w;
            g_rec[beg + i].p = e4;
        }
        sp = wsum4(sp);
        d4 = wsum4(d4);
        float c = fmaxf((float)deg, 1.f);
        float4 esf;
        esf.x = __expf(lrelu(an.x + ad.x + sp.x / c));
        esf.y = __expf(lrelu(an.y + ad.y + sp.y / c));
        esf.z = __expf(lrelu(an.z + ad.z + sp.z / c));
        esf.w = __expf(lrelu(an.w + ad.w + sp.w / c));
        d4.x += esf.x; d4.y += esf.y; d4.z += esf.z; d4.w += esf.w;
        float4 inv;
        inv.x = 1.f / (d4.x + 1e-16f); inv.y = 1.f / (d4.y + 1e-16f);
        inv.z = 1.f / (d4.z + 1e-16f); inv.w = 1.f / (d4.w + 1e-16f);
        float invA = lo ? inv.x : inv.y;
        float invB = lo ? inv.z : inv.w;
        if (deg > CAP) __threadfence_block();
        __syncwarp();

        float acc0 = 0.f, acc1 = 0.f;
        int j = 0;
        for (; j + 2 <= dc; j += 2) {
            float4 a0 = s_al[wi][j];
            float4 a1 = s_al[wi][j + 1];
            const float* r0 = &g_xh[(size_t)s_src[wi][j] * 64];
            const float* r1 = &g_xh[(size_t)s_src[wi][j + 1] * 64];
            float x00 = r0[lane], x01 = r0[32 + lane];
            float x10 = r1[lane], x11 = r1[32 + lane];
            acc0 += (lo ? a0.x : a0.y) * invA * x00;
            acc1 += (lo ? a0.z : a0.w) * invB * x01;
            acc0 += (lo ? a1.x : a1.y) * invA * x10;
            acc1 += (lo ? a1.z : a1.w) * invB * x11;
        }
        if (j < dc) {
            float4 a0 = s_al[wi][j];
            const float* r0 = &g_xh[(size_t)s_src[wi][j] * 64];
            acc0 += (lo ? a0.x : a0.y) * invA * r0[lane];
            acc1 += (lo ? a0.z : a0.w) * invB * r0[32 + lane];
        }
        for (int k = CAP; k < deg; k++) {   // rare spill path
            float4 a0 = g_rec[beg + k].p;
            const float* r0 = &g_xh[(size_t)g_rec[beg + k].src * 64];
            acc0 += (lo ? a0.x : a0.y) * invA * r0[lane];
            acc1 += (lo ? a0.z : a0.w) * invB * r0[32 + lane];
        }
        {   // self-loop contribution
            const float* rn = &g_xh[(size_t)n * 64];
            acc0 += (lo ? esf.x : esf.y) * invA * rn[lane];
            acc1 += (lo ? esf.z : esf.w) * invB * rn[32 + lane];
        }
        out[(size_t)n * 64 + lane]      = acc0 + bs0;
        out[(size_t)n * 64 + 32 + lane] = acc1 + bs1;
        __syncwarp();
    }
}

// -----------------------------------------------------------------------------
extern "C" void kernel_launch(void* const* d_in, const int* in_sizes, int n_in,
                              void* d_out, int out_size) {
    (void)n_in; (void)out_size;
    const float* x        = (const float*)d_in[0];
    const int*   ei       = (const int*)d_in[1];
    const float* ea       = (const float*)d_in[2];
    const float* W        = (const float*)d_in[3];
    const float* We       = (const float*)d_in[4];
    const float* att_src  = (const float*)d_in[5];
    const float* att_dst  = (const float*)d_in[6];
    const float* att_edge = (const float*)d_in[7];
    const float* bias     = (const float*)d_in[8];
    float* out = (float*)d_out;

    int N = in_sizes[0] / 128;   // x is [N,128]
    int E = in_sizes[1] / 2;     // edge_index is [2,E]
    int NB = (N + SCAN_B - 1) / SCAN_B;

    k_initv <<<(N + 255) / 256, 256>>>(We, att_edge, W, N);  // 0
    k_hist  <<<(E + 255) / 256, 256>>>(ei, E);               // 1
    k_scanA <<<NB, SCAN_B>>>(N);                             // 2
    k_xh    <<<(N + 63) / 64, 256>>>(x, att_src, att_dst, N); // 3 <- profiled
    k_scanB <<<1, 1024>>>(NB);                               // 4
    k_scanC <<<NB, SCAN_B>>>(N);                             // 5
    k_edge_p<<<(E + 127) / 128, 128>>>(ea, ei, E);           // 6
    k_node  <<<1480, 256>>>(bias, out, N);                   // 7
}